// round 5
// baseline (speedup 1.0000x reference)
#include <cuda_runtime.h>
#include <cstdint>

// Problem shape (fixed for this dataset entry)
#define B_ 4
#define C_ 32
#define H_ 256
#define W_ 512
#define D_ 48

#define WT   128            // w-tile per block
#define TW   (WT + D_)      // 176: h1 tile width (window overhang)
#define TWP  (TW + 1)       // 177: padded stride -> conflict-free (gcd(17,32)=1)
#define NTHREADS 256

// --- packed f32x2 helpers (FFMA2 is PTX-only; ptxas never auto-fuses) ---
__device__ __forceinline__ void fma2(unsigned long long &acc,
                                     unsigned long long a,
                                     unsigned long long b) {
    asm("fma.rn.f32x2 %0, %1, %2, %0;" : "+l"(acc) : "l"(a), "l"(b));
}
__device__ __forceinline__ unsigned long long pack2(float lo, float hi) {
    unsigned long long r;
    asm("mov.b64 %0, {%1, %2};"
        : "=l"(r) : "r"(__float_as_uint(lo)), "r"(__float_as_uint(hi)));
    return r;
}

__global__ void __launch_bounds__(NTHREADS, 3)
dense_warp_kernel(const float* __restrict__ h1,
                  const float* __restrict__ cost,
                  float* __restrict__ out) {
    __shared__ __align__(16) float cost_s[D_ * WT];   // 24 KB
    __shared__ __align__(16) float h1_s[C_ * TWP];    // 22.6 KB

    const int bx    = blockIdx.x;
    const int wt    = bx & 3;                 // W_/WT = 4 tiles
    const int h     = (bx >> 2) & (H_ - 1);
    const int b     = bx >> 10;               // /(4*256)
    const int wbase = wt * WT;
    const int tid   = threadIdx.x;

    // ---- load cost tile [D_ x WT] (float4, coalesced) ----
    {
        const float* cbase = cost + ((size_t)(b * D_) * H_ + h) * W_ + wbase;
        #pragma unroll
        for (int idx = tid; idx < (D_ * WT) / 4; idx += NTHREADS) {
            int dd = idx >> 5;               // WT/4 = 32 float4 per row
            int ww = (idx & 31) << 2;
            *(float4*)&cost_s[dd * WT + ww] =
                *(const float4*)&cbase[(size_t)dd * (H_ * W_) + ww];
        }
    }
    // ---- load h1 tile [C_ x TW], zero-padded past W (handles w+d >= W) ----
    {
        const float* hbase = h1 + ((size_t)(b * C_) * H_ + h) * W_ + wbase;
        for (int idx = tid; idx < C_ * TW; idx += NTHREADS) {
            int cc = idx / TW;
            int x  = idx - cc * TW;
            float v = 0.0f;
            if (wbase + x < W_) v = hbase[(size_t)cc * (H_ * W_) + x];
            h1_s[cc * TWP + x] = v;
        }
    }
    __syncthreads();

    // warp = 32 channels at one w-sublane: cost reads broadcast, h1 conflict-free
    const int c  = tid & 31;
    const int wl = tid >> 5;        // 0..7
    const int w0 = wl * 16;

    const float* hr = &h1_s[c * TWP + w0];

    // Packed sliding windows over h1 (relative to w0):
    //   E[m] = (h1[2m],   h1[2m+1])   -> used on even d = 2t   (entries t..t+7)
    //   O[m] = (h1[2m+1], h1[2m+2])   -> used on odd  d = 2t+1 (entries t..t+7)
    unsigned long long E[8], O[8], acc[8];
    {
        float f[16];
        #pragma unroll
        for (int j = 0; j < 16; j++) f[j] = hr[j];
        #pragma unroll
        for (int k = 0; k < 8; k++) E[k] = pack2(f[2 * k], f[2 * k + 1]);
        #pragma unroll
        for (int k = 0; k < 7; k++) O[k] = pack2(f[2 * k + 1], f[2 * k + 2]);
        O[7] = 0ull;                 // built in round 0 before first odd use
        #pragma unroll
        for (int j = 0; j < 8; j++) acc[j] = 0ull;

        float prev_e1 = f[15];

        // Fully unrolled: 24 rounds of (even d=2t, odd d=2t+1).
        // Static ring slots + immediate SMEM offsets.
        #pragma unroll
        for (int t = 0; t < D_ / 2; t++) {
            // ---- even step d = 2t: pairs (w+d, w+d+1) = E[t+k] ----
            const ulonglong2* cp =
                (const ulonglong2*)&cost_s[(2 * t) * WT + w0];
            ulonglong2 q0 = cp[0], q1 = cp[1], q2 = cp[2], q3 = cp[3];
            fma2(acc[0], q0.x, E[(t + 0) & 7]);
            fma2(acc[1], q0.y, E[(t + 1) & 7]);
            fma2(acc[2], q1.x, E[(t + 2) & 7]);
            fma2(acc[3], q1.y, E[(t + 3) & 7]);
            fma2(acc[4], q2.x, E[(t + 4) & 7]);
            fma2(acc[5], q2.y, E[(t + 5) & 7]);
            fma2(acc[6], q3.x, E[(t + 6) & 7]);
            fma2(acc[7], q3.y, E[(t + 7) & 7]);

            // refill O[t+7] = (h1[2t+15], h1[2t+16]) = (prev_e1, e0)
            float e0 = hr[16 + 2 * t];
            O[(t + 7) & 7] = pack2(prev_e1, e0);

            // ---- odd step d = 2t+1: pairs = O[t+k] ----
            const ulonglong2* cq =
                (const ulonglong2*)&cost_s[(2 * t + 1) * WT + w0];
            ulonglong2 r0 = cq[0], r1 = cq[1], r2 = cq[2], r3 = cq[3];
            fma2(acc[0], r0.x, O[(t + 0) & 7]);
            fma2(acc[1], r0.y, O[(t + 1) & 7]);
            fma2(acc[2], r1.x, O[(t + 2) & 7]);
            fma2(acc[3], r1.y, O[(t + 3) & 7]);
            fma2(acc[4], r2.x, O[(t + 4) & 7]);
            fma2(acc[5], r2.y, O[(t + 5) & 7]);
            fma2(acc[6], r3.x, O[(t + 6) & 7]);
            fma2(acc[7], r3.y, O[(t + 7) & 7]);

            // refill E[t+8] = (h1[2t+16], h1[2t+17]) = (e0, e1)
            float e1 = hr[17 + 2 * t];
            E[t & 7] = pack2(e0, e1);
            prev_e1 = e1;
        }
    }

    // ---- store 16 contiguous floats per thread (4x STG.128) ----
    float* orow = out + (((size_t)b * C_ + c) * H_ + h) * W_ + wbase + w0;
    ulonglong2* ov = (ulonglong2*)orow;
    ov[0] = make_ulonglong2(acc[0], acc[1]);
    ov[1] = make_ulonglong2(acc[2], acc[3]);
    ov[2] = make_ulonglong2(acc[4], acc[5]);
    ov[3] = make_ulonglong2(acc[6], acc[7]);
}

extern "C" void kernel_launch(void* const* d_in, const int* in_sizes, int n_in,
                              void* d_out, int out_size) {
    (void)in_sizes; (void)n_in; (void)out_size;
    const float* h1   = (const float*)d_in[0];
    const float* cost = (const float*)d_in[1];
    float* out        = (float*)d_out;

    const int nblocks = B_ * H_ * (W_ / WT);   // 4096
    dense_warp_kernel<<<nblocks, NTHREADS>>>(h1, cost, out);
}

// round 7
// speedup vs baseline: 1.0393x; 1.0393x over previous
#include <cuda_runtime.h>
#include <cstdint>

// Problem shape (fixed for this dataset entry)
#define B_ 4
#define C_ 32
#define H_ 256
#define W_ 512
#define D_ 48

#define WT   128            // w-tile per block
#define TW   (WT + D_)      // 176: h1 tile width (window overhang)
#define TWP  177            // padded row stride (odd -> conflict-free refills)
#define NTHREADS 128
#define CH_T 4              // channels per thread (stride 8)
#define W_T  8              // w outputs per thread

// --- packed f32x2 helpers (FFMA2 is PTX-only; ptxas never auto-fuses) ---
__device__ __forceinline__ void fma2(unsigned long long &acc,
                                     unsigned long long a,
                                     unsigned long long b) {
    asm("fma.rn.f32x2 %0, %1, %2, %0;" : "+l"(acc) : "l"(a), "l"(b));
}
__device__ __forceinline__ unsigned long long pack2(float lo, float hi) {
    unsigned long long r;
    asm("mov.b64 %0, {%1, %2};"
        : "=l"(r) : "r"(__float_as_uint(lo)), "r"(__float_as_uint(hi)));
    return r;
}

__global__ void __launch_bounds__(NTHREADS, 4)
dense_warp_kernel(const float* __restrict__ h1,
                  const float* __restrict__ cost,
                  float* __restrict__ out) {
    __shared__ __align__(16) float cost_s[D_ * WT];   // 24 KB
    __shared__ __align__(16) float h1_s[C_ * TWP];    // 22.7 KB

    const int bx    = blockIdx.x;
    const int wt    = bx & 3;                 // W_/WT = 4 tiles
    const int h     = (bx >> 2) & (H_ - 1);
    const int b     = bx >> 10;               // /(4*256)
    const int wbase = wt * WT;
    const int tid   = threadIdx.x;

    // ---- load cost tile [D_ x WT] (float4, coalesced) ----
    {
        const float* cbase = cost + ((size_t)(b * D_) * H_ + h) * W_ + wbase;
        #pragma unroll
        for (int it = 0; it < (D_ * WT) / (4 * NTHREADS); it++) {   // 12 iters
            int idx = it * NTHREADS + tid;
            int dd = idx >> 5;               // WT/4 = 32 float4 per row
            int ww = (idx & 31) << 2;
            *(float4*)&cost_s[dd * WT + ww] =
                *(const float4*)&cbase[(size_t)dd * (H_ * W_) + ww];
        }
    }
    // ---- load h1 tile [C_ x TW], zero-padded past W (handles w+d >= W) ----
    {
        const float* hbase = h1 + ((size_t)(b * C_) * H_ + h) * W_ + wbase;
        for (int idx = tid; idx < C_ * TW; idx += NTHREADS) {
            int cc = idx / TW;
            int x  = idx - cc * TW;
            float v = 0.0f;
            if (wbase + x < W_) v = hbase[(size_t)cc * (H_ * W_) + x];
            h1_s[cc * TWP + x] = v;
        }
    }
    __syncthreads();

    // lane layout: c0 = lane&7 (channel base), wsl = lane>>3 (w sub-slice).
    // thread tile: channels {c0, c0+8, c0+16, c0+24} x w [w0, w0+8)
    // -> cost regs reused across 4 channels; refill LDS.32 banks
    //    17*c0 + 8*wsl + const are provably distinct within a warp.
    const int c0  = tid & 7;
    const int wsg = tid >> 3;        // 0..15
    const int w0  = wsg * W_T;       // 0..120

    const float* hr = &h1_s[c0 * TWP + w0];   // + i*(8*TWP) per channel slot

    // Packed sliding windows per channel (relative to w0):
    //   E[m] = (h1[2m],   h1[2m+1])  used on even d = 2t (entries t..t+3)
    //   O[m] = (h1[2m+1], h1[2m+2])  used on odd  d = 2t+1 (entries t..t+3)
    unsigned long long E[CH_T][4], O[CH_T][4], acc[CH_T][4];
    float prev[CH_T];                // carries h1[2t+8] into round t

    #pragma unroll
    for (int i = 0; i < CH_T; i++) {
        float f[9];
        #pragma unroll
        for (int j = 0; j < 9; j++) f[j] = hr[i * (8 * TWP) + j];
        E[i][0] = pack2(f[0], f[1]);
        E[i][1] = pack2(f[2], f[3]);
        E[i][2] = pack2(f[4], f[5]);
        E[i][3] = pack2(f[6], f[7]);
        O[i][0] = pack2(f[1], f[2]);
        O[i][1] = pack2(f[3], f[4]);
        O[i][2] = pack2(f[5], f[6]);
        O[i][3] = pack2(f[7], f[8]);
        prev[i] = f[8];
        acc[i][0] = acc[i][1] = acc[i][2] = acc[i][3] = 0ull;
    }

    // 24 fully-unrolled rounds of (even d=2t, odd d=2t+1); static ring slots.
    #pragma unroll
    for (int t = 0; t < D_ / 2; t++) {
        // new h1 values for this round's refills (independent loads, issue early)
        float u[CH_T], v[CH_T];
        #pragma unroll
        for (int i = 0; i < CH_T; i++) {
            u[i] = hr[i * (8 * TWP) + 9  + 2 * t];   // h1[2t+9]
            v[i] = hr[i * (8 * TWP) + 10 + 2 * t];   // h1[2t+10]
        }

        // ---- even step d = 2t ----
        {
            const ulonglong2* cp =
                (const ulonglong2*)&cost_s[(2 * t) * WT + w0];
            ulonglong2 q0 = cp[0], q1 = cp[1];
            #pragma unroll
            for (int i = 0; i < CH_T; i++) {
                fma2(acc[i][0], q0.x, E[i][(t + 0) & 3]);
                fma2(acc[i][1], q0.y, E[i][(t + 1) & 3]);
                fma2(acc[i][2], q1.x, E[i][(t + 2) & 3]);
                fma2(acc[i][3], q1.y, E[i][(t + 3) & 3]);
            }
        }
        // refill E[t+4] = (h1[2t+8], h1[2t+9]) = (prev, u); slot t&3 now dead
        #pragma unroll
        for (int i = 0; i < CH_T; i++)
            E[i][t & 3] = pack2(prev[i], u[i]);

        // ---- odd step d = 2t+1 ----
        {
            const ulonglong2* cq =
                (const ulonglong2*)&cost_s[(2 * t + 1) * WT + w0];
            ulonglong2 r0 = cq[0], r1 = cq[1];
            #pragma unroll
            for (int i = 0; i < CH_T; i++) {
                fma2(acc[i][0], r0.x, O[i][(t + 0) & 3]);
                fma2(acc[i][1], r0.y, O[i][(t + 1) & 3]);
                fma2(acc[i][2], r1.x, O[i][(t + 2) & 3]);
                fma2(acc[i][3], r1.y, O[i][(t + 3) & 3]);
            }
        }
        // refill O[t+4] = (h1[2t+9], h1[2t+10]) = (u, v); carry prev = v
        #pragma unroll
        for (int i = 0; i < CH_T; i++) {
            O[i][t & 3] = pack2(u[i], v[i]);
            prev[i] = v[i];
        }
    }

    // ---- store: 4 channels x 8 contiguous floats (2x STG.128 each) ----
    #pragma unroll
    for (int i = 0; i < CH_T; i++) {
        int c = c0 + 8 * i;
        float* orow = out + (((size_t)b * C_ + c) * H_ + h) * W_ + wbase + w0;
        ulonglong2* ov = (ulonglong2*)orow;
        ov[0] = make_ulonglong2(acc[i][0], acc[i][1]);
        ov[1] = make_ulonglong2(acc[i][2], acc[i][3]);
    }
}

extern "C" void kernel_launch(void* const* d_in, const int* in_sizes, int n_in,
                              void* d_out, int out_size) {
    (void)in_sizes; (void)n_in; (void)out_size;
    const float* h1   = (const float*)d_in[0];
    const float* cost = (const float*)d_in[1];
    float* out        = (float*)d_out;

    const int nblocks = B_ * H_ * (W_ / WT);   // 4096
    dense_warp_kernel<<<nblocks, NTHREADS>>>(h1, cost, out);
}

// round 8
// speedup vs baseline: 1.5652x; 1.5060x over previous
#include <cuda_runtime.h>
#include <cstdint>

// Problem shape (fixed for this dataset entry)
#define B_ 4
#define C_ 32
#define H_ 256
#define W_ 512
#define D_ 48

#define WT   128            // w-tile per block
#define TW   (WT + D_)      // 176: h1 tile width (window overhang)
#define TWP  178            // padded row stride: even (float2-aligned), 18 mod 32 -> conflict-free refills
#define NTHREADS 256
#define CH_T 2              // channels per thread (stride 16)
#define W_T  8              // w outputs per thread
#define ROUNDS (D_ / 2)     // 24

// --- packed f32x2 helpers (FFMA2 is PTX-only; ptxas never auto-fuses) ---
__device__ __forceinline__ void fma2(unsigned long long &acc,
                                     unsigned long long a,
                                     unsigned long long b) {
    asm("fma.rn.f32x2 %0, %1, %2, %0;" : "+l"(acc) : "l"(a), "l"(b));
}
__device__ __forceinline__ unsigned long long pack2(float lo, float hi) {
    unsigned long long r;
    asm("mov.b64 %0, {%1, %2};"
        : "=l"(r) : "r"(__float_as_uint(lo)), "r"(__float_as_uint(hi)));
    return r;
}

__global__ void __launch_bounds__(NTHREADS, 3)
dense_warp_kernel(const float* __restrict__ h1,
                  const float* __restrict__ cost,
                  float* __restrict__ out) {
    __shared__ __align__(16) float cost_s[D_ * WT];   // 24 KB
    __shared__ __align__(16) float h1_s[C_ * TWP];    // 22.8 KB

    const int bx    = blockIdx.x;
    const int wt    = bx & 3;                 // W_/WT = 4 tiles
    const int h     = (bx >> 2) & (H_ - 1);
    const int b     = bx >> 10;               // /(4*256)
    const int wbase = wt * WT;
    const int tid   = threadIdx.x;

    // ---- load cost tile [D_ x WT] (float4, coalesced): 1536 float4 / 256 thr ----
    {
        const float* cbase = cost + ((size_t)(b * D_) * H_ + h) * W_ + wbase;
        #pragma unroll
        for (int it = 0; it < 6; it++) {
            int idx = it * NTHREADS + tid;
            int dd = idx >> 5;               // WT/4 = 32 float4 per row
            int ww = (idx & 31) << 2;
            *(float4*)&cost_s[dd * WT + ww] =
                *(const float4*)&cbase[(size_t)dd * (H_ * W_) + ww];
        }
    }
    // ---- load h1 tile [C_ x TW] as float2, zero-padded past W ----
    {
        const float* hbase = h1 + ((size_t)(b * C_) * H_ + h) * W_ + wbase;
        #pragma unroll
        for (int it = 0; it < (C_ * (TW / 2)) / NTHREADS; it++) {   // 11 iters
            int idx = it * NTHREADS + tid;
            int cc = idx / (TW / 2);
            int x  = (idx - cc * (TW / 2)) * 2;
            float2 v = make_float2(0.0f, 0.0f);
            if (wbase + x < W_)
                v = *(const float2*)&hbase[(size_t)cc * (H_ * W_) + x];
            *(float2*)&h1_s[cc * TWP + x] = v;
        }
    }
    __syncthreads();

    // lane layout: c0 = lane&15 (channel base), wsl = lane>>4 (w sub-slice).
    // thread tile: channels {c0, c0+16} x w [w0, w0+8)
    const int lane = tid & 31;
    const int wid  = tid >> 5;                 // 0..7
    const int c0   = lane & 15;
    const int wsl  = lane >> 4;                // 0..1
    const int w0   = wid * 16 + wsl * 8;       // 0..120

    const float* hr = &h1_s[c0 * TWP + w0];    // + i*(16*TWP) per channel slot

    // Packed sliding windows per channel (relative to w0):
    //   E[m] = (h1[2m],   h1[2m+1])  used on even d = 2t (entries t..t+3)
    //   O[m] = (h1[2m+1], h1[2m+2])  used on odd  d = 2t+1 (entries t..t+3)
    unsigned long long E[CH_T][4], O[CH_T][4], acc[CH_T][4];
    float prev[CH_T];                // carries h1[2t+8] into round t

    #pragma unroll
    for (int i = 0; i < CH_T; i++) {
        float f[9];
        #pragma unroll
        for (int j = 0; j < 9; j++) f[j] = hr[i * (16 * TWP) + j];
        E[i][0] = pack2(f[0], f[1]);
        E[i][1] = pack2(f[2], f[3]);
        E[i][2] = pack2(f[4], f[5]);
        E[i][3] = pack2(f[6], f[7]);
        O[i][0] = pack2(f[1], f[2]);
        O[i][1] = pack2(f[3], f[4]);
        O[i][2] = pack2(f[5], f[6]);
        O[i][3] = pack2(f[7], f[8]);
        prev[i] = f[8];
        acc[i][0] = acc[i][1] = acc[i][2] = acc[i][3] = 0ull;
    }

    // Prefetch even-step cost for round 0 (d = 0).
    ulonglong2 qa = ((const ulonglong2*)&cost_s[0 * WT + w0])[0];
    ulonglong2 qb = ((const ulonglong2*)&cost_s[0 * WT + w0])[1];

    // 24 fully-unrolled rounds of (even d=2t, odd d=2t+1); static ring slots.
    // Even-step cost (qa,qb) was loaded one full round earlier -> LDS latency hidden.
    #pragma unroll
    for (int t = 0; t < ROUNDS; t++) {
        // issue this round's other loads first (use is ~15+ instrs away)
        float u[CH_T], v[CH_T];
        #pragma unroll
        for (int i = 0; i < CH_T; i++) {
            u[i] = hr[i * (16 * TWP) + 9  + 2 * t];   // h1[2t+9]
            if (t < ROUNDS - 1)
                v[i] = hr[i * (16 * TWP) + 10 + 2 * t];   // h1[2t+10]
        }
        const ulonglong2* cq = (const ulonglong2*)&cost_s[(2 * t + 1) * WT + w0];
        ulonglong2 r0 = cq[0], r1 = cq[1];

        // prefetch next round's even cost (dead slot reuse on last round)
        const int nrow = (t < ROUNDS - 1) ? (2 * t + 2) : 0;
        const ulonglong2* cn = (const ulonglong2*)&cost_s[nrow * WT + w0];
        ulonglong2 n0 = cn[0], n1 = cn[1];

        // ---- even step d = 2t ----
        #pragma unroll
        for (int i = 0; i < CH_T; i++) {
            fma2(acc[i][0], qa.x, E[i][(t + 0) & 3]);
            fma2(acc[i][1], qa.y, E[i][(t + 1) & 3]);
            fma2(acc[i][2], qb.x, E[i][(t + 2) & 3]);
            fma2(acc[i][3], qb.y, E[i][(t + 3) & 3]);
        }
        // refill E[t+4] = (h1[2t+8], h1[2t+9]) = (prev, u)
        if (t < ROUNDS - 1) {
            #pragma unroll
            for (int i = 0; i < CH_T; i++)
                E[i][t & 3] = pack2(prev[i], u[i]);
        }

        // ---- odd step d = 2t+1 ----
        #pragma unroll
        for (int i = 0; i < CH_T; i++) {
            fma2(acc[i][0], r0.x, O[i][(t + 0) & 3]);
            fma2(acc[i][1], r0.y, O[i][(t + 1) & 3]);
            fma2(acc[i][2], r1.x, O[i][(t + 2) & 3]);
            fma2(acc[i][3], r1.y, O[i][(t + 3) & 3]);
        }
        // refill O[t+4] = (h1[2t+9], h1[2t+10]) = (u, v); carry prev = v
        if (t < ROUNDS - 1) {
            #pragma unroll
            for (int i = 0; i < CH_T; i++) {
                O[i][t & 3] = pack2(u[i], v[i]);
                prev[i] = v[i];
            }
        }
        qa = n0; qb = n1;
    }

    // ---- store: 2 channels x 8 contiguous floats (2x STG.128 each) ----
    #pragma unroll
    for (int i = 0; i < CH_T; i++) {
        int c = c0 + 16 * i;
        float* orow = out + (((size_t)b * C_ + c) * H_ + h) * W_ + wbase + w0;
        ulonglong2* ov = (ulonglong2*)orow;
        ov[0] = make_ulonglong2(acc[i][0], acc[i][1]);
        ov[1] = make_ulonglong2(acc[i][2], acc[i][3]);
    }
}

extern "C" void kernel_launch(void* const* d_in, const int* in_sizes, int n_in,
                              void* d_out, int out_size) {
    (void)in_sizes; (void)n_in; (void)out_size;
    const float* h1   = (const float*)d_in[0];
    const float* cost = (const float*)d_in[1];
    float* out        = (float*)d_out;

    const int nblocks = B_ * H_ * (W_ / WT);   // 4096
    dense_warp_kernel<<<nblocks, NTHREADS>>>(h1, cost, out);
}